// round 14
// baseline (speedup 1.0000x reference)
#include <cuda_runtime.h>
#include <math.h>

#define N_ATOMS 512
#define NQC     8
#define NT      16      // targets per block
#define NS      16      // sources per chunk
#define NCH     32      // source chunks
#define TPB     128     // NT * NQC
#define NTQ     (N_ATOMS * NQC)   // 4096
#define NTB     (N_ATOMS / NT)    // 32 target blocks

// compact accumulators: [18][tq] (288 KB, L2-resident). Zero at process start;
// finalizer CTAs re-zero after consuming, so every replay sees clean state.
__device__ float        g_acc[18 * NTQ];
__device__ unsigned int g_cnt[NTB];   // per-target-block completion counters
__device__ unsigned int g_fin;        // finalizer-done counter
__device__ float        g_pot;        // pot accumulator

__global__ __launch_bounds__(TPB, 8)
void ewald_kernel(const float* __restrict__ gq, const float* __restrict__ gr,
                  const float* __restrict__ gu, const float* __restrict__ gQ,
                  const float* __restrict__ gkap, const float* __restrict__ gal,
                  float* __restrict__ out)
{
    __shared__ __align__(16) float s_sr[NS * 3];
    __shared__ __align__(16) float s_tr[NT * 3];
    // packed source-channel data, stride 12: {q,ux,uy,uz | S00,S01,S02,S11 | S12,S22,trq,0}
    __shared__ __align__(16) float s_src[NS * NQC * 12];    // 6 KB
    __shared__ __align__(16) float s_pair[NS * NT * 8];     // 8 KB {g,c1,c2,c3,c4,dx,dy,dz}
    __shared__ float s_red[4];

    const int tid = threadIdx.x;
    const int bx  = blockIdx.x;

    // ================= FINALIZER CTAs (blockIdx.y == NCH) =================
    if (blockIdx.y == NCH) {
        const int tqi = bx * TPB + tid;   // NT*NQC == TPB

        // prefetch inputs pairs never writes (overlaps with compute CTAs)
        const float qv  = gq[tqi];
        const float kap = gkap[tqi];
        const float al  = gal[tqi];
        const float ux = gu[tqi * 3 + 0], uy = gu[tqi * 3 + 1], uz = gu[tqi * 3 + 2];
        float Qpv[9];
#pragma unroll
        for (int k = 0; k < 9; k++) Qpv[k] = gQ[tqi * 9 + k];

        // wait for all NCH chunk CTAs of this target block (acquire pairs with
        // the compute CTAs' release-red on g_cnt)
        if (tid == 0) {
            unsigned int v;
            do {
                asm volatile("ld.acquire.gpu.global.u32 %0, [%1];"
                             : "=r"(v) : "l"(&g_cnt[bx]) : "memory");
                if (v < NCH) __nanosleep(64);
            } while (v < NCH);
        }
        __syncthreads();

        float acc[18];
#pragma unroll
        for (int k = 0; k < 18; k++)
            acc[k] = __ldcg(&g_acc[k * NTQ + tqi]);
#pragma unroll
        for (int k = 0; k < 18; k++)
            g_acc[k * NTQ + tqi] = 0.0f;          // self-clean for next replay

        const float A0 = acc[0], A1 = acc[1], A2 = acc[2];
        const float Eux = acc[3], Euy = acc[4], Euz = acc[5];
        const float EQx = acc[6], EQy = acc[7], EQz = acc[8];
        const float Efx = acc[9], Efy = acc[10], Efz = acc[11];
        const float Qxx = acc[12], Qxy = acc[13], Qxz = acc[14];
        const float Qyy = acc[15], Qyz = acc[16], Qzz = acc[17];

        const float ephi = A0 + A1 + A2;
        out[1 + tqi] = -kap * ephi;                               // q_induced

        const float ex = Efx + Eux + EQx;
        const float ey = Efy + Euy + EQy;
        const float ez = Efz + Euz + EQz;
        out[1 + NTQ + tqi * 3 + 0] = al * ex;                     // u_induced
        out[1 + NTQ + tqi * 3 + 1] = al * ey;
        out[1 + NTQ + tqi * 3 + 2] = al * ez;

        const float qQQ = Qpv[0] * Qxx + Qpv[4] * Qyy + Qpv[8] * Qzz
                        + (Qpv[1] + Qpv[3]) * Qxy + (Qpv[2] + Qpv[6]) * Qxz
                        + (Qpv[5] + Qpv[7]) * Qyz;
        const float uEu = ux * Eux + uy * Euy + uz * Euz;
        const float uEQ = ux * EQx + uy * EQy + uz * EQz;
        const float e2  = ex * ex + ey * ey + ez * ez;

        float pot = 0.5f * A0 * qv + A1 * qv - 0.5f * uEu + qv * A2
                  + 0.125f * qQQ - uEQ
                  - 0.5f * kap * ephi * ephi
                  - 0.5f * al * e2;

#pragma unroll
        for (int off = 16; off > 0; off >>= 1)
            pot += __shfl_xor_sync(0xFFFFFFFFu, pot, off);
        if ((tid & 31) == 0) s_red[tid >> 5] = pot;
        __syncthreads();
        if (tid == 0) {
            g_cnt[bx] = 0u;                       // self-clean counter
            const float bp = s_red[0] + s_red[1] + s_red[2] + s_red[3];
            atomicAdd(&g_pot, bp);
            __threadfence();
            const unsigned int of = atomicAdd(&g_fin, 1u);
            if (of == NTB - 1) {                  // globally last finalizer
                const float tot = atomicAdd(&g_pot, 0.0f);  // coherent read
                out[0] = tot;
                g_pot = 0.0f;                     // self-clean
                g_fin = 0u;
            }
        }
        return;
    }

    // ================= COMPUTE CTAs (blockIdx.y < NCH) =====================
    const int t0 = bx * NT;
    const int s0 = blockIdx.y * NS;

    // ---- phase 1: stage source + target data into smem ----
    for (int i = tid; i < NS * 3; i += TPB) s_sr[i] = gr[s0 * 3 + i];
    for (int i = tid; i < NT * 3; i += TPB) s_tr[i] = gr[t0 * 3 + i];
    for (int i = tid; i < NS * NQC; i += TPB) {
        const float qv = gq[s0 * NQC + i];
        const float* up = gu + (s0 * NQC + i) * 3;
        const float* Qp = gQ + (s0 * NQC + i) * 9;
        const float q00 = Qp[0], q01 = Qp[1], q02 = Qp[2];
        const float q10 = Qp[3], q11 = Qp[4], q12 = Qp[5];
        const float q20 = Qp[6], q21 = Qp[7], q22 = Qp[8];
        float4* d = (float4*)&s_src[i * 12];
        d[0] = make_float4(qv, up[0], up[1], up[2]);
        d[1] = make_float4(q00 + q00, q01 + q10, q02 + q20, q11 + q11);
        d[2] = make_float4(q12 + q21, q22 + q22, q00 + q11 + q22, 0.f);
    }
    __syncthreads();

    // ---- phase 2: pair scalar kernels (g, D1..D4)*nc and displacement ----
    const float A_ERF = 0.70710678118654752f;                         // 1/sqrt(2)
    const float NCE = (float)(90.4756 / (2.0 * 3.14159265358979323846));
    const float NCG = (float)((90.4756 / (2.0 * 3.14159265358979323846))
                              * 0.79788456080286536);                 // nc * 2a/sqrt(pi)

#pragma unroll
    for (int p = tid; p < NS * NT; p += TPB) {
        const int s  = p >> 4;
        const int tl = p & 15;
        float dx = s_tr[tl * 3 + 0] - s_sr[s * 3 + 0];
        float dy = s_tr[tl * 3 + 1] - s_sr[s * 3 + 1];
        float dz = s_tr[tl * 3 + 2] - s_sr[s * 3 + 2];
        float g = 0.f, c1 = 0.f, c2 = 0.f, c3 = 0.f, c4 = 0.f;
        if (t0 + tl != s0 + s) {
            float r2 = dx * dx + dy * dy + dz * dz;
            float rr = sqrtf(r2);
            float E  = NCE * erff(A_ERF * rr);
            float G  = NCG * expf(-0.5f * rr * rr);
            float ir = 1.0f / rr;
            float ir2 = ir * ir,  ir3 = ir2 * ir,  ir4 = ir2 * ir2, ir5 = ir4 * ir;
            float ir6 = ir4 * ir2, ir7 = ir6 * ir, ir8 = ir4 * ir4, ir9 = ir8 * ir;
            g  = E * ir;
            c1 = G * ir2 - E * ir3;
            c2 = 3.0f * E * ir5 - 3.0f * G * ir4 - G * ir2;                       // 2*a2 = 1
            c3 = -15.0f * E * ir7 + 15.0f * G * ir6 + 5.0f * G * ir4 + G * ir2;   // 10*a2=5, 4*a2^2=1
            c4 = 105.0f * E * ir9 - 105.0f * G * ir8 - 35.0f * G * ir6
                 - 7.0f * G * ir4 - G * ir2;                                      // 70a2=35, 28a2^2=7, 8a2^3=1
        }
        float4* op = (float4*)&s_pair[p * 8];
        op[0] = make_float4(g, c1, c2, c3);
        op[1] = make_float4(c4, dx, dy, dz);
    }
    __syncthreads();

    // ---- phase 3: per-(target, channel) accumulation over the source tile ----
    const int tl = tid >> 3;
    const int qc = tid & 7;

    float A0 = 0.f, A1 = 0.f, A2 = 0.f;
    float Eux = 0.f, Euy = 0.f, Euz = 0.f;
    float EQx = 0.f, EQy = 0.f, EQz = 0.f;
    float Efx = 0.f, Efy = 0.f, Efz = 0.f;
    float Qxx = 0.f, Qxy = 0.f, Qxz = 0.f, Qyy = 0.f, Qyz = 0.f, Qzz = 0.f;

#pragma unroll 8
    for (int s = 0; s < NS; s++) {
        const float4 pa = *(const float4*)&s_pair[(s * NT + tl) * 8];
        const float4 pb = *(const float4*)&s_pair[(s * NT + tl) * 8 + 4];
        const float g  = pa.x, c1 = pa.y, c2 = pa.z, c3 = pa.w;
        const float c4 = pb.x, dx = pb.y, dy = pb.z, dz = pb.w;
        const float4 f0 = *(const float4*)&s_src[(s * NQC + qc) * 12];
        const float4 f1 = *(const float4*)&s_src[(s * NQC + qc) * 12 + 4];
        const float4 f2 = *(const float4*)&s_src[(s * NQC + qc) * 12 + 8];
        const float qs = f0.x, ux = f0.y, uy = f0.z, uz = f0.w;
        const float S00 = f1.x, S01 = f1.y, S02 = f1.z, S11 = f1.w;
        const float S12 = f2.x, S22 = f2.y, trq = f2.z;

        const float ud  = fmaf(ux, dx, fmaf(uy, dy, uz * dz));
        // s = S·d  (== Q·d + Qᵀ·d);  dQd = ½ dᵀS d
        const float sx = fmaf(S00, dx, fmaf(S01, dy, S02 * dz));
        const float sy = fmaf(S01, dx, fmaf(S11, dy, S12 * dz));
        const float sz = fmaf(S02, dx, fmaf(S12, dy, S22 * dz));
        const float dQd = 0.5f * fmaf(dx, sx, fmaf(dy, sy, dz * sz));

        // potentials at target
        A0 = fmaf(g, qs, A0);
        A1 = fmaf(-c1, ud, A1);
        A2 = fmaf(0.5f * c2, dQd, A2);
        A2 = fmaf(0.5f * c1, trq, A2);

        // E_u (dipole field)
        const float t2u = c2 * ud;
        Eux = fmaf(t2u, dx, fmaf(c1, ux, Eux));
        Euy = fmaf(t2u, dy, fmaf(c1, uy, Euy));
        Euz = fmaf(t2u, dz, fmaf(c1, uz, Euz));

        // shared: cD = c3*dQd + c2*trq  (also = -2*Aq)
        const float cD = fmaf(c3, dQd, c2 * trq);

        // E_Q (quadrupole field):  Aq = -0.5*cD, Bq = -0.5*c2
        const float Aq = -0.5f * cD;
        const float Bq = -0.5f * c2;
        EQx = fmaf(Aq, dx, fmaf(Bq, sx, EQx));
        EQy = fmaf(Aq, dy, fmaf(Bq, sy, EQy));
        EQz = fmaf(Aq, dz, fmaf(Bq, sz, EQz));

        // field from charges
        const float t1q = c1 * qs;
        Efx = fmaf(-t1q, dx, Efx);
        Efy = fmaf(-t1q, dy, Efy);
        Efz = fmaf(-t1q, dz, Efz);

        // QQ (symmetric 3x3)
        const float cA = fmaf(c4, dQd, c3 * trq);
        const float hx = c3 * sx, hy = c3 * sy, hz = c3 * sz;
        Qxx = fmaf(cA, dx * dx, Qxx);
        Qxx = fmaf(hx + hx, dx, Qxx);
        Qxx = fmaf(c2, S00, Qxx + cD);
        Qyy = fmaf(cA, dy * dy, Qyy);
        Qyy = fmaf(hy + hy, dy, Qyy);
        Qyy = fmaf(c2, S11, Qyy + cD);
        Qzz = fmaf(cA, dz * dz, Qzz);
        Qzz = fmaf(hz + hz, dz, Qzz);
        Qzz = fmaf(c2, S22, Qzz + cD);
        Qxy = fmaf(cA, dx * dy, Qxy);
        Qxy = fmaf(hx, dy, Qxy);
        Qxy = fmaf(hy, dx, Qxy);
        Qxy = fmaf(c2, S01, Qxy);
        Qxz = fmaf(cA, dx * dz, Qxz);
        Qxz = fmaf(hx, dz, Qxz);
        Qxz = fmaf(hz, dx, Qxz);
        Qxz = fmaf(c2, S02, Qxz);
        Qyz = fmaf(cA, dy * dz, Qyz);
        Qyz = fmaf(hy, dz, Qyz);
        Qyz = fmaf(hz, dy, Qyz);
        Qyz = fmaf(c2, S12, Qyz);
    }

    // ---- accumulate partials (fire-and-forget red ops), then release-count ----
    {
        const int tqi = (t0 + tl) * NQC + qc;
        const float acc[18] = {A0, A1, A2, Eux, Euy, Euz, EQx, EQy, EQz,
                               Efx, Efy, Efz, Qxx, Qxy, Qxz, Qyy, Qyz, Qzz};
#pragma unroll
        for (int k = 0; k < 18; k++)
            atomicAdd(&g_acc[k * NTQ + tqi], acc[k]);
    }
    __syncthreads();            // all threads' REDs issued before the count
    if (tid == 0) {
        // release-red: orders this CTA's g_acc atomics before the count bump,
        // pairing with the finalizer's ld.acquire. Fire-and-forget: no stall.
        asm volatile("red.release.gpu.global.add.u32 [%0], 1;"
                     :: "l"(&g_cnt[bx]) : "memory");
    }
}

extern "C" void kernel_launch(void* const* d_in, const int* in_sizes, int n_in,
                              void* d_out, int out_size)
{
    (void)in_sizes; (void)n_in; (void)out_size;
    const float* q     = (const float*)d_in[0];
    const float* r     = (const float*)d_in[1];
    // d_in[2] = cell (zero -> realspace branch), d_in[3] = batch: unused
    const float* u     = (const float*)d_in[4];
    const float* quad  = (const float*)d_in[5];
    const float* kappa = (const float*)d_in[6];
    const float* alpha = (const float*)d_in[7];
    float* out = (float*)d_out;

    // Single grid: 32x32 compute CTAs + 32 finalizer CTAs (y == NCH), all
    // co-resident in one wave (1056 <= 1184 capacity at 8 CTAs/SM). Finalizers
    // prefetch inputs, spin on g_cnt with acquire, then write all outputs.
    ewald_kernel<<<dim3(NTB, NCH + 1), TPB>>>(q, r, u, quad, kappa, alpha, out);
}

// round 15
// speedup vs baseline: 1.2687x; 1.2687x over previous
#include <cuda_runtime.h>
#include <math.h>

#define N_ATOMS 512
#define NQC     8
#define NT      16      // targets per block
#define NS      16      // sources per chunk
#define NCH     32      // source chunks
#define TPB     128     // NT * NQC
#define NTQ     (N_ATOMS * NQC)   // 4096
#define NTB     (N_ATOMS / NT)    // 32 target blocks

// compact accumulators: [18][tq] (288 KB, L2-resident). Zero at process start;
// finalize re-zeroes after consuming, so every replay sees clean state.
__device__ float g_acc[18 * NTQ];

__global__ __launch_bounds__(TPB, 8)
void pairs_kernel(const float* __restrict__ gq, const float* __restrict__ gr,
                  const float* __restrict__ gu, const float* __restrict__ gQ,
                  float* __restrict__ out)
{
    __shared__ __align__(16) float s_sr[NS * 3];
    __shared__ __align__(16) float s_tr[NT * 3];
    // packed source-channel data, stride 12:
    // {q,ux,uy,uz | H00,H01,H02,H11 | H12,H22,trq,0}  with H = (Q+Q^T)/2
    __shared__ __align__(16) float s_src[NS * NQC * 12];    // 6 KB
    __shared__ __align__(16) float s_pair[NS * NT * 8];     // 8 KB {g,c1,c2,c3,c4,dx,dy,dz}

    const int tid = threadIdx.x;
    const int t0  = blockIdx.x * NT;
    const int s0  = blockIdx.y * NS;

    if (blockIdx.x == 0 && blockIdx.y == 0 && tid == 0)
        out[0] = 0.0f;   // pot accumulator, consumed by finalize after this grid completes

    // ---- phase 1: stage source + target data into smem ----
    for (int i = tid; i < NS * 3; i += TPB) s_sr[i] = gr[s0 * 3 + i];
    for (int i = tid; i < NT * 3; i += TPB) s_tr[i] = gr[t0 * 3 + i];
    for (int i = tid; i < NS * NQC; i += TPB) {
        const float qv = gq[s0 * NQC + i];
        const float* up = gu + (s0 * NQC + i) * 3;
        const float* Qp = gQ + (s0 * NQC + i) * 9;
        const float q00 = Qp[0], q01 = Qp[1], q02 = Qp[2];
        const float q10 = Qp[3], q11 = Qp[4], q12 = Qp[5];
        const float q20 = Qp[6], q21 = Qp[7], q22 = Qp[8];
        float4* d = (float4*)&s_src[i * 12];
        d[0] = make_float4(qv, up[0], up[1], up[2]);
        d[1] = make_float4(q00, 0.5f * (q01 + q10), 0.5f * (q02 + q20), q11);
        d[2] = make_float4(0.5f * (q12 + q21), q22, q00 + q11 + q22, 0.f);
    }
    __syncthreads();

    // ---- phase 2: pair scalar kernels (g, D1..D4)*nc and displacement ----
    const float A_ERF = 0.70710678118654752f;                         // 1/sqrt(2)
    const float NCE = (float)(90.4756 / (2.0 * 3.14159265358979323846));
    const float NCG = (float)((90.4756 / (2.0 * 3.14159265358979323846))
                              * 0.79788456080286536);                 // nc * 2a/sqrt(pi)

#pragma unroll
    for (int p = tid; p < NS * NT; p += TPB) {
        const int s  = p >> 4;
        const int tl = p & 15;
        float dx = s_tr[tl * 3 + 0] - s_sr[s * 3 + 0];
        float dy = s_tr[tl * 3 + 1] - s_sr[s * 3 + 1];
        float dz = s_tr[tl * 3 + 2] - s_sr[s * 3 + 2];
        float g = 0.f, c1 = 0.f, c2 = 0.f, c3 = 0.f, c4 = 0.f;
        if (t0 + tl != s0 + s) {
            float r2 = dx * dx + dy * dy + dz * dz;
            float rr = sqrtf(r2);
            float E  = NCE * erff(A_ERF * rr);
            float G  = NCG * expf(-0.5f * rr * rr);
            float ir = 1.0f / rr;
            float ir2 = ir * ir,  ir3 = ir2 * ir,  ir4 = ir2 * ir2, ir5 = ir4 * ir;
            float ir6 = ir4 * ir2, ir7 = ir6 * ir, ir8 = ir4 * ir4, ir9 = ir8 * ir;
            g  = E * ir;
            c1 = G * ir2 - E * ir3;
            c2 = 3.0f * E * ir5 - 3.0f * G * ir4 - G * ir2;                       // 2*a2 = 1
            c3 = -15.0f * E * ir7 + 15.0f * G * ir6 + 5.0f * G * ir4 + G * ir2;   // 10*a2=5, 4*a2^2=1
            c4 = 105.0f * E * ir9 - 105.0f * G * ir8 - 35.0f * G * ir6
                 - 7.0f * G * ir4 - G * ir2;                                      // 70a2=35, 28a2^2=7, 8a2^3=1
        }
        float4* op = (float4*)&s_pair[p * 8];
        op[0] = make_float4(g, c1, c2, c3);
        op[1] = make_float4(c4, dx, dy, dz);
    }
    __syncthreads();

    // ---- phase 3: per-(target, channel) accumulation over the source tile ----
    const int tl = tid >> 3;
    const int qc = tid & 7;

    float A0 = 0.f, A1 = 0.f, A2 = 0.f;          // A2 stores 2x value (finalize *0.5)
    float Eux = 0.f, Euy = 0.f, Euz = 0.f;
    float EQx = 0.f, EQy = 0.f, EQz = 0.f;       // stores -2x value (finalize *-0.5)
    float Efx = 0.f, Efy = 0.f, Efz = 0.f;
    float Qxx = 0.f, Qxy = 0.f, Qxz = 0.f, Qyy = 0.f, Qyz = 0.f, Qzz = 0.f;

#pragma unroll 8
    for (int s = 0; s < NS; s++) {
        const float4 pa = *(const float4*)&s_pair[(s * NT + tl) * 8];
        const float4 pb = *(const float4*)&s_pair[(s * NT + tl) * 8 + 4];
        const float g  = pa.x, c1 = pa.y, c2 = pa.z, c3 = pa.w;
        const float c4 = pb.x, dx = pb.y, dy = pb.z, dz = pb.w;
        const float4 f0 = *(const float4*)&s_src[(s * NQC + qc) * 12];
        const float4 f1 = *(const float4*)&s_src[(s * NQC + qc) * 12 + 4];
        const float4 f2 = *(const float4*)&s_src[(s * NQC + qc) * 12 + 8];
        const float qs = f0.x, ux = f0.y, uy = f0.z, uz = f0.w;
        const float H00 = f1.x, H01 = f1.y, H02 = f1.z, H11 = f1.w;
        const float H12 = f2.x, H22 = f2.y, trq = f2.z;

        const float ud  = fmaf(ux, dx, fmaf(uy, dy, uz * dz));
        // sh = H·d = (Q·d + Qᵀ·d)/2 ;  dQd = dᵀH d  (exactly the reference dQd)
        const float shx = fmaf(H00, dx, fmaf(H01, dy, H02 * dz));
        const float shy = fmaf(H01, dx, fmaf(H11, dy, H12 * dz));
        const float shz = fmaf(H02, dx, fmaf(H12, dy, H22 * dz));
        const float dQd = fmaf(dx, shx, fmaf(dy, shy, dz * shz));

        // potentials at target (A2 accumulated at 2x; finalize scales by 0.5)
        A0 = fmaf(g, qs, A0);
        A1 = fmaf(-c1, ud, A1);
        A2 = fmaf(c2, dQd, A2);
        A2 = fmaf(c1, trq, A2);

        // E_u (dipole field)
        const float t2u = c2 * ud;
        Eux = fmaf(t2u, dx, fmaf(c1, ux, Eux));
        Euy = fmaf(t2u, dy, fmaf(c1, uy, Euy));
        Euz = fmaf(t2u, dz, fmaf(c1, uz, Euz));

        // shared scalars
        const float cD  = fmaf(c3, dQd, c2 * trq);
        const float cA  = fmaf(c4, dQd, c3 * trq);
        const float c22 = c2 + c2;
        const float c32 = c3 + c3;
        const float cAh = 0.5f * cA;

        // E_Q accumulated at -2x: EQ' += cD·d + c22·sh  (finalize * -0.5)
        EQx = fmaf(cD, dx, fmaf(c22, shx, EQx));
        EQy = fmaf(cD, dy, fmaf(c22, shy, EQy));
        EQz = fmaf(cD, dz, fmaf(c22, shz, EQz));

        // field from charges
        const float t1q = c1 * qs;
        Efx = fmaf(-t1q, dx, Efx);
        Efy = fmaf(-t1q, dy, Efy);
        Efz = fmaf(-t1q, dz, Efz);

        // QQ via m-vector: m = ½cA·d + c3·s = cAh·d + c32·sh
        // QQ_ab += m_a d_b + m_b d_a + c22·H_ab + cD·δ_ab
        const float mx = fmaf(cAh, dx, c32 * shx);
        const float my = fmaf(cAh, dy, c32 * shy);
        const float mz = fmaf(cAh, dz, c32 * shz);

        Qxx = fmaf(mx + mx, dx, Qxx + cD);
        Qxx = fmaf(c22, H00, Qxx);
        Qyy = fmaf(my + my, dy, Qyy + cD);
        Qyy = fmaf(c22, H11, Qyy);
        Qzz = fmaf(mz + mz, dz, Qzz + cD);
        Qzz = fmaf(c22, H22, Qzz);
        Qxy = fmaf(mx, dy, Qxy);
        Qxy = fmaf(my, dx, Qxy);
        Qxy = fmaf(c22, H01, Qxy);
        Qxz = fmaf(mx, dz, Qxz);
        Qxz = fmaf(mz, dx, Qxz);
        Qxz = fmaf(c22, H02, Qxz);
        Qyz = fmaf(my, dz, Qyz);
        Qyz = fmaf(mz, dy, Qyz);
        Qyz = fmaf(c22, H12, Qyz);
    }

    // ---- accumulate partials into compact L2-resident array (red ops) ----
    const int tqi = (t0 + tl) * NQC + qc;
    const float acc[18] = {A0, A1, A2, Eux, Euy, Euz, EQx, EQy, EQz,
                           Efx, Efy, Efz, Qxx, Qxy, Qxz, Qyy, Qyz, Qzz};
#pragma unroll
    for (int k = 0; k < 18; k++)
        atomicAdd(&g_acc[k * NTQ + tqi], acc[k]);
}

// PDL secondary: starts while pairs drains, prefetches inputs that pairs does
// not write, then grid-syncs before touching g_acc / out.
__global__ __launch_bounds__(32)
void finalize_kernel(const float* __restrict__ gq, const float* __restrict__ gu,
                     const float* __restrict__ gQ, const float* __restrict__ gkap,
                     const float* __restrict__ gal, float* __restrict__ out)
{
    const int tqi = blockIdx.x * 32 + threadIdx.x;

    // prefetch inputs independent of pairs' outputs
    const float qv  = gq[tqi];
    const float kap = gkap[tqi];
    const float al  = gal[tqi];
    const float ux = gu[tqi * 3 + 0], uy = gu[tqi * 3 + 1], uz = gu[tqi * 3 + 2];
    float Qpv[9];
#pragma unroll
    for (int k = 0; k < 9; k++) Qpv[k] = gQ[tqi * 9 + k];

    // wait for pairs_kernel completion (all its atomics + out[0]=0 visible)
    cudaGridDependencySynchronize();

    float acc[18];
#pragma unroll
    for (int k = 0; k < 18; k++)
        acc[k] = g_acc[k * NTQ + tqi];
    // re-zero for the next invocation (self-cleaning accumulator)
#pragma unroll
    for (int k = 0; k < 18; k++)
        g_acc[k * NTQ + tqi] = 0.0f;

    const float A0 = acc[0], A1 = acc[1];
    const float A2 = 0.5f * acc[2];               // 0.5 folded out of pairs
    const float Eux = acc[3], Euy = acc[4], Euz = acc[5];
    const float EQx = -0.5f * acc[6];             // -0.5 folded out of pairs
    const float EQy = -0.5f * acc[7];
    const float EQz = -0.5f * acc[8];
    const float Efx = acc[9], Efy = acc[10], Efz = acc[11];
    const float Qxx = acc[12], Qxy = acc[13], Qxz = acc[14];
    const float Qyy = acc[15], Qyz = acc[16], Qzz = acc[17];

    const float ephi = A0 + A1 + A2;
    out[1 + tqi] = -kap * ephi;                               // q_induced

    const float ex = Efx + Eux + EQx;
    const float ey = Efy + Euy + EQy;
    const float ez = Efz + Euz + EQz;
    out[1 + NTQ + tqi * 3 + 0] = al * ex;                     // u_induced
    out[1 + NTQ + tqi * 3 + 1] = al * ey;
    out[1 + NTQ + tqi * 3 + 2] = al * ez;

    const float qQQ = Qpv[0] * Qxx + Qpv[4] * Qyy + Qpv[8] * Qzz
                    + (Qpv[1] + Qpv[3]) * Qxy + (Qpv[2] + Qpv[6]) * Qxz
                    + (Qpv[5] + Qpv[7]) * Qyz;
    const float uEu = ux * Eux + uy * Euy + uz * Euz;
    const float uEQ = ux * EQx + uy * EQy + uz * EQz;
    const float e2  = ex * ex + ey * ey + ez * ez;

    float pot = 0.5f * A0 * qv + A1 * qv - 0.5f * uEu + qv * A2
              + 0.125f * qQQ - uEQ
              - 0.5f * kap * ephi * ephi
              - 0.5f * al * e2;

    // warp-shuffle reduction, one atomic per block
#pragma unroll
    for (int off = 16; off > 0; off >>= 1)
        pot += __shfl_xor_sync(0xFFFFFFFFu, pot, off);
    if (threadIdx.x == 0) atomicAdd(&out[0], pot);
}

extern "C" void kernel_launch(void* const* d_in, const int* in_sizes, int n_in,
                              void* d_out, int out_size)
{
    (void)in_sizes; (void)n_in; (void)out_size;
    const float* q     = (const float*)d_in[0];
    const float* r     = (const float*)d_in[1];
    // d_in[2] = cell (zero -> realspace branch), d_in[3] = batch: unused
    const float* u     = (const float*)d_in[4];
    const float* quad  = (const float*)d_in[5];
    const float* kappa = (const float*)d_in[6];
    const float* alpha = (const float*)d_in[7];
    float* out = (float*)d_out;

    pairs_kernel<<<dim3(NTB, NCH), TPB>>>(q, r, u, quad, out);

    // finalize with Programmatic Dependent Launch (R8 configuration).
    cudaLaunchConfig_t cfg = {};
    cfg.gridDim  = dim3(NTQ / 32, 1, 1);
    cfg.blockDim = dim3(32, 1, 1);
    cfg.dynamicSmemBytes = 0;
    cfg.stream = 0;
    cudaLaunchAttribute attrs[1];
    attrs[0].id = cudaLaunchAttributeProgrammaticStreamSerialization;
    attrs[0].val.programmaticStreamSerializationAllowed = 1;
    cfg.attrs = attrs;
    cfg.numAttrs = 1;
    cudaLaunchKernelEx(&cfg, finalize_kernel, q, u, quad, kappa, alpha, out);
}